// round 16
// baseline (speedup 1.0000x reference)
#include <cuda_runtime.h>
#include <cuda_fp16.h>
#include <cuda_bf16.h>
#include <cstdint>

// Problem constants (fixed by the reference)
#define BB    2048
#define VV    2048
#define CC    512
#define MM    8
#define HH    16
#define EPSF  1e-6f
#define NBLK  148          // persistent: one block per SM
#define PAIRS (BB / 2)     // 1024 row-pairs
#define TPB   1024         // 2 threads per channel (H-split) -> 32 warps/SM

__device__ __forceinline__ float ex2_fast(float x) {
    float y;
    asm("ex2.approx.f32 %0, %1;" : "=f"(y) : "f"(x));
    return y;
}
__device__ __forceinline__ float rcp_fast(float x) {
    float y;
    asm("rcp.approx.f32 %0, %1;" : "=f"(y) : "f"(x));
    return y;
}
// Named *_fast to avoid colliding with cuda_fp16.hpp's h2tanh().
__device__ __forceinline__ __half2 h2tanh_fast(__half2 x) {
    unsigned xi = *reinterpret_cast<unsigned*>(&x), yi;
    asm("tanh.approx.f16x2 %0, %1;" : "=r"(yi) : "r"(xi));
    return *reinterpret_cast<__half2*>(&yi);
}
__device__ __forceinline__ void cpasync16(void* smem_ptr, const float* g) {
    unsigned int saddr = (unsigned int)__cvta_generic_to_shared(smem_ptr);
    asm volatile("cp.async.cg.shared.global [%0], [%1], 16;" :: "r"(saddr), "l"(g));
}
#define CP_COMMIT() asm volatile("cp.async.commit_group;" ::: "memory")
#define CP_WAIT0()  asm volatile("cp.async.wait_group 0;" ::: "memory")

// Stall-surgery on the H-split base (R13): 1024 threads, 2 per channel
// (even thread h=0..7, odd h=8..15), 2 rows/iter in f16x2 lanes, all tanh
// on MUFU. Changes vs R13, targeting the measured 58% stall fraction:
//  (1) epilogue uses x_own[m] saved via SEL in the m-loop instead of
//      re-gathering 8 scattered LDS per thread;
//  (2) dual f16 accumulators halve the serial HFMA2 chain per m.
__global__ __launch_bounds__(TPB, 1) void gradoptim_attn_kernel(
    const float* __restrict__ preds,
    const int*   __restrict__ mask_ids,
    const float* __restrict__ W1,   // (C, 2, H)
    const float* __restrict__ b1,   // (C, H)
    const float* __restrict__ W2,   // (C, H)
    const float* __restrict__ b2,   // (C,)
    float*       __restrict__ out)  // (B, V)
{
    __shared__ float rows[2][2][VV];   // [ring buf][row in pair][col] = 32 KB

    const int t    = threadIdx.x;
    const int c    = t >> 1;           // channel
    const int half = t & 1;            // 0: h=0..7 / row0 epilogue; 1: h=8..15 / row1

    // ---- Own 8 h-values of the per-channel weights ----
    const float4* W1f4 = reinterpret_cast<const float4*>(W1);
    const float4* b1f4 = reinterpret_cast<const float4*>(b1);
    const float4* W2f4 = reinterpret_cast<const float4*>(W2);
    float4 a0  = W1f4[c * 8 + half * 2 + 0];      // W1[c,0,own 0..3]
    float4 a1  = W1f4[c * 8 + half * 2 + 1];      // W1[c,0,own 4..7]
    float4 q0  = W1f4[c * 8 + 4 + half * 2 + 0];  // W1[c,1,own 0..3]
    float4 q1  = W1f4[c * 8 + 4 + half * 2 + 1];
    float4 bv0 = b1f4[c * 4 + half * 2 + 0];
    float4 bv1 = b1f4[c * 4 + half * 2 + 1];
    float4 s0  = W2f4[c * 4 + half * 2 + 0];
    float4 s1  = W2f4[c * 4 + half * 2 + 1];

    __half2 w1bh[8], w2h[8], w1a_pk[4], b1_pk[4];
    w1bh[0] = __float2half2_rn(q0.x); w1bh[1] = __float2half2_rn(q0.y);
    w1bh[2] = __float2half2_rn(q0.z); w1bh[3] = __float2half2_rn(q0.w);
    w1bh[4] = __float2half2_rn(q1.x); w1bh[5] = __float2half2_rn(q1.y);
    w1bh[6] = __float2half2_rn(q1.z); w1bh[7] = __float2half2_rn(q1.w);
    w2h[0] = __float2half2_rn(s0.x);  w2h[1] = __float2half2_rn(s0.y);
    w2h[2] = __float2half2_rn(s0.z);  w2h[3] = __float2half2_rn(s0.w);
    w2h[4] = __float2half2_rn(s1.x);  w2h[5] = __float2half2_rn(s1.y);
    w2h[6] = __float2half2_rn(s1.z);  w2h[7] = __float2half2_rn(s1.w);
    w1a_pk[0] = __floats2half2_rn(a0.x, a0.y);  w1a_pk[1] = __floats2half2_rn(a0.z, a0.w);
    w1a_pk[2] = __floats2half2_rn(a1.x, a1.y);  w1a_pk[3] = __floats2half2_rn(a1.z, a1.w);
    b1_pk[0]  = __floats2half2_rn(bv0.x, bv0.y); b1_pk[1] = __floats2half2_rn(bv0.z, bv0.w);
    b1_pk[2]  = __floats2half2_rn(bv1.x, bv1.y); b1_pk[3] = __floats2half2_rn(bv1.z, bv1.w);

    const float b2c = b2[c];

    int idx[MM];
    {
        const int4* mi = reinterpret_cast<const int4*>(mask_ids + (size_t)c * MM);
        int4 i0 = mi[0], i1 = mi[1];
        idx[0] = i0.x; idx[1] = i0.y; idx[2] = i0.z; idx[3] = i0.w;
        idx[4] = i1.x; idx[5] = i1.y; idx[6] = i1.z; idx[7] = i1.w;
    }

    const float LOG2E = 1.4426950408889634f;
    const int sr = t >> 9;        // staging: which row of the pair (0/1)
    const int sj = t & 511;       // staging: float4 column

    // ---- Prologue: stage first pair into ring buf 0 (1 float4/thread) ----
    int p = blockIdx.x;
    if (p < PAIRS) {
        cpasync16(&rows[0][sr][sj * 4], preds + (size_t)(2 * p + sr) * VV + sj * 4);
        CP_COMMIT();
    }

    int buf = 0;
    while (p < PAIRS) {
        CP_WAIT0();
        __syncthreads();

        const int pn = p + NBLK;
        if (pn < PAIRS) {
            cpasync16(&rows[buf ^ 1][sr][sj * 4],
                      preds + (size_t)(2 * pn + sr) * VV + sj * 4);
            CP_COMMIT();
        }

        // Tail copy [512,2048): 2 rows x 384 float4 = 768, threads t<768.
        if (t < 768) {
            const int rr = (t >= 384) ? 1 : 0;
            const int jj = t - rr * 384;
            float4 v = reinterpret_cast<float4*>(rows[buf][rr])[128 + jj];
            reinterpret_cast<float4*>(out + (size_t)(2 * p + rr) * VV)[128 + jj] = v;
        }

        // ---- u for own 8 h-values; f16x2 lanes = (row0, row1) ----
        const float ha0 = rows[buf][0][c];
        const float ha1 = rows[buf][1][c];
        const __half2 ha2 = __floats2half2_rn(ha0, ha1);
        __half2 uh[8];
        #pragma unroll
        for (int i = 0; i < 4; i++) {
            uh[2*i]   = __hfma2(ha2, __low2half2(w1a_pk[i]),  __low2half2(b1_pk[i]));
            uh[2*i+1] = __hfma2(ha2, __high2half2(w1a_pk[i]), __high2half2(b1_pk[i]));
        }

        // ---- Partial scores (own 8 h) + save own-row x via SEL ----
        __half2 sc_h2[MM];
        float   x_own[MM];           // this thread's row value; no re-gather later
        #pragma unroll
        for (int m = 0; m < MM; m++) {
            const float xf0 = rows[buf][0][idx[m]];
            const float xf1 = rows[buf][1][idx[m]];
            x_own[m] = half ? xf1 : xf0;               // SEL, not LDS
            __half2 x2 = __floats2half2_rn(xf0, xf1);
            __half2 aE = __float2half2_rn(0.0f);
            __half2 aO = aE;
            #pragma unroll
            for (int h = 0; h < 8; h += 2) {           // dual acc chains
                aE = __hfma2(w2h[h],     h2tanh_fast(__hfma2(x2, w1bh[h],     uh[h])),     aE);
                aO = __hfma2(w2h[h + 1], h2tanh_fast(__hfma2(x2, w1bh[h + 1], uh[h + 1])), aO);
            }
            __half2 acc = __hadd2(aE, aO);
            unsigned au = *reinterpret_cast<unsigned*>(&acc);
            unsigned pu = __shfl_xor_sync(0xFFFFFFFFu, au, 1);
            sc_h2[m] = __hadd2(acc, *reinterpret_cast<__half2*>(&pu));
        }

        // ---- Epilogue: own row only; all inputs already in registers ----
        float sc[MM];
        #pragma unroll
        for (int m = 0; m < MM; m++)
            sc[m] = (half ? __high2float(sc_h2[m]) : __low2float(sc_h2[m])) + b2c;

        float mx = sc[0];
        #pragma unroll
        for (int m = 1; m < MM; m++) mx = fmaxf(mx, sc[m]);

        float sum = 0.0f, ws = 0.0f;
        #pragma unroll
        for (int m = 0; m < MM; m++) {
            float e = ex2_fast((sc[m] - mx) * LOG2E);
            sum += e;
            ws   = fmaf(e, x_own[m], ws);
        }
        const float ha_own = half ? ha1 : ha0;
        const float corrected = fmaxf(ha_own, ws * rcp_fast(sum) + EPSF);

        out[(size_t)(2 * p + half) * VV + c] = corrected;

        buf ^= 1;
        p = pn;
    }
}

extern "C" void kernel_launch(void* const* d_in, const int* in_sizes, int n_in,
                              void* d_out, int out_size) {
    (void)in_sizes; (void)n_in; (void)out_size;
    const float* preds    = (const float*)d_in[0];
    // d_in[1] = ground_truth (unused by the reference)
    const int*   mask_ids = (const int*)  d_in[2];
    const float* W1       = (const float*)d_in[3];
    const float* b1       = (const float*)d_in[4];
    const float* W2       = (const float*)d_in[5];
    const float* b2       = (const float*)d_in[6];
    float*       out      = (float*)d_out;

    gradoptim_attn_kernel<<<NBLK, TPB>>>(preds, mask_ids, W1, b1, W2, b2, out);
}